// round 9
// baseline (speedup 1.0000x reference)
#include <cuda_runtime.h>
#include <cuda_bf16.h>

#define BB  4
#define CD  48
#define HW  16384
#define D1  384
#define OC4 1536

__device__ float g_qkv0[(size_t)BB * OC4 * HW];
__device__ float g_qkv [(size_t)BB * OC4 * HW];
__device__ float g_ao  [(size_t)BB * D1  * HW];
__device__ float g_red [BB * 3 * D1];
__device__ float g_L   [BB * D1];
__device__ float g_Spart[(size_t)BB * 8 * 64 * 2304];
__device__ float g_A   [(size_t)BB * 8 * 2304];

// K1: 1x1 conv 48->1536, scalar FFMA. grid(128,12,4), 256thr, dyn smem 49152
__global__ __launch_bounds__(256) void k1_conv1x1(const float* __restrict__ x,
                                                  const float* __restrict__ qw) {
    extern __shared__ float sm[];
    float* Ws = sm;              // [48][128] weights, o fast
    float* Xs = sm + 48 * 128;   // [48][128] pixels
    int b = blockIdx.z, ot = blockIdx.y, pt = blockIdx.x, t = threadIdx.x;
    for (int idx = t; idx < 48 * 128; idx += 256) {
        int o = idx / 48, k = idx % 48;
        Ws[k * 128 + o] = qw[(ot * 128 + o) * 48 + k];
    }
    const float* xb = x + (size_t)b * CD * HW + pt * 128;
    for (int idx = t; idx < 48 * 128; idx += 256) {
        int k = idx / 128, p = idx % 128;
        Xs[k * 128 + p] = xb[(size_t)k * HW + p];
    }
    __syncthreads();
    int tp = t & 15, ot8 = t >> 4;      // tp: pixel lane, ot8: 8-channel group
    float acc[8][8];
#pragma unroll
    for (int i = 0; i < 8; i++)
#pragma unroll
        for (int j = 0; j < 8; j++) acc[i][j] = 0.0f;
    for (int k = 0; k < 48; k++) {
        float xv[8], wv[8];
#pragma unroll
        for (int j = 0; j < 8; j++) xv[j] = Xs[k * 128 + tp + 16 * j];
#pragma unroll
        for (int i = 0; i < 8; i++) wv[i] = Ws[k * 128 + ot8 * 8 + i];
#pragma unroll
        for (int i = 0; i < 8; i++)
#pragma unroll
            for (int j = 0; j < 8; j++) acc[i][j] = fmaf(wv[i], xv[j], acc[i][j]);
    }
    float* outb = g_qkv0 + ((size_t)b * OC4 + ot * 128) * HW + pt * 128;
#pragma unroll
    for (int i = 0; i < 8; i++) {
        float* orow = outb + (size_t)(ot8 * 8 + i) * HW;
#pragma unroll
        for (int j = 0; j < 8; j++) orow[tp + 16 * j] = acc[i][j];
    }
}

// K2: grouped 3x3 conv, 192 groups x 8ch, scalar FFMA. grid(4,192,4), 256thr, dyn smem 141696
__global__ __launch_bounds__(256) void k2_dwconv(const float* __restrict__ dw) {
    extern __shared__ float sm[];
    float* sx = sm;                 // [8][66][66] halo
    float* ws = sm + 8 * 66 * 66;   // [8 il][9 tap][8 oc]
    int tileid = blockIdx.x, g = blockIdx.y, b = blockIdx.z, t = threadIdx.x;
    int ty0 = (tileid >> 1) * 64, tx0 = (tileid & 1) * 64;
    const float* inb = g_qkv0 + ((size_t)b * OC4 + g * 8) * HW;
    for (int idx = t; idx < 8 * 66 * 66; idx += 256) {
        int ch = idx / (66 * 66), rem = idx % (66 * 66);
        int yy = rem / 66, xx = rem % 66;
        int gy = ty0 + yy - 1, gx = tx0 + xx - 1;
        float v = 0.0f;
        if (gy >= 0 && gy < 128 && gx >= 0 && gx < 128) v = inb[(size_t)ch * HW + gy * 128 + gx];
        sx[idx] = v;
    }
    for (int idx = t; idx < 576; idx += 256) {
        int il = idx / 72, rem = idx % 72, tap = rem / 8, oc = rem % 8;
        ws[idx] = dw[(g * 8 + oc) * 72 + il * 9 + tap];
    }
    __syncthreads();
    float* outb = g_qkv + ((size_t)b * OC4 + g * 8) * HW;
    for (int s0 = 0; s0 < 2; s0++) {
        int s = t + s0 * 256, sy = s >> 3, x0 = (s & 7) * 8;
        float acc[8][8];   // [oc][px]
#pragma unroll
        for (int oc = 0; oc < 8; oc++)
#pragma unroll
            for (int px = 0; px < 8; px++) acc[oc][px] = 0.0f;
        for (int il = 0; il < 8; il++) {
            const float* base = sx + il * 66 * 66;
#pragma unroll
            for (int ky = 0; ky < 3; ky++) {
                const float* row = base + (sy + ky) * 66 + x0;
                float d[10];
#pragma unroll
                for (int m = 0; m < 10; m++) d[m] = row[m];
#pragma unroll
                for (int kx = 0; kx < 3; kx++) {
                    const float* wrow = ws + il * 72 + (ky * 3 + kx) * 8;
                    float w[8];
#pragma unroll
                    for (int oc = 0; oc < 8; oc++) w[oc] = wrow[oc];
#pragma unroll
                    for (int oc = 0; oc < 8; oc++)
#pragma unroll
                        for (int px = 0; px < 8; px++)
                            acc[oc][px] = fmaf(d[px + kx], w[oc], acc[oc][px]);
                }
            }
        }
        int off = (ty0 + sy) * 128 + tx0 + x0;
#pragma unroll
        for (int oc = 0; oc < 8; oc++) {
            float4* o4 = (float4*)(outb + (size_t)oc * HW + off);
            o4[0] = make_float4(acc[oc][0], acc[oc][1], acc[oc][2], acc[oc][3]);
            o4[1] = make_float4(acc[oc][4], acc[oc][5], acc[oc][6], acc[oc][7]);
        }
    }
}

// K3: q sumsq / k sumsq / l sum. grid(384,3,4), 256thr
__global__ void k3_reduce() {
    int ch = blockIdx.x, type = blockIdx.y, b = blockIdx.z, t = threadIdx.x;
    int base_ch = (type == 0) ? ch : (type == 1) ? 384 + ch : 1152 + ch;
    const float* src = g_qkv + ((size_t)b * OC4 + base_ch) * HW;
    float s = 0.0f;
    for (int p = t; p < HW; p += 256) { float v = src[p]; s += (type == 2) ? v : v * v; }
    __shared__ float red[256];
    red[t] = s; __syncthreads();
    for (int off = 128; off > 0; off >>= 1) { if (t < off) red[t] += red[t + off]; __syncthreads(); }
    if (t == 0) g_red[(b * 3 + type) * D1 + ch] = red[0];
}

// K4: channel MLP -> L (swish). grid(4), 384thr
__global__ void k4_mlp(const float* __restrict__ fc1w, const float* __restrict__ fc1b,
                       const float* __restrict__ fc2w, const float* __restrict__ fc2b) {
    int b = blockIdx.x, t = threadIdx.x;
    __shared__ float avg[384], y1[24];
    avg[t] = g_red[(b * 3 + 2) * D1 + t] * (1.0f / 16384.0f);
    __syncthreads();
    if (t < 24) {
        float s = fc1b[t];
        for (int c = 0; c < 384; c++) s += fc1w[t * 384 + c] * avg[c];
        y1[t] = fmaxf(s, 0.0f);
    }
    __syncthreads();
    float s = fc2b[t];
    for (int j = 0; j < 24; j++) s += fc2w[t * 24 + j] * y1[j];
    g_L[b * D1 + t] = s / (1.0f + expf(-s));
}

// K5: raw q.k^T partials over 256-pixel chunks. grid(64,32), 256thr, dyn smem 98688
__global__ __launch_bounds__(256) void k5_scores() {
    extern __shared__ float sm[];
    float* qs = sm;            // [48][257]
    float* ks = sm + 48 * 257;
    int ck = blockIdx.x, bh = blockIdx.y, b = bh >> 3, h = bh & 7;
    int p0 = ck * 256, t = threadIdx.x;
    const float* qb = g_qkv + ((size_t)b * OC4 + h * 48) * HW + p0;
    const float* kb = g_qkv + ((size_t)b * OC4 + 384 + h * 48) * HW + p0;
    for (int idx = t; idx < 48 * 256; idx += 256) {
        int c = idx >> 8, p = idx & 255;
        qs[c * 257 + p] = qb[(size_t)c * HW + p];
        ks[c * 257 + p] = kb[(size_t)c * HW + p];
    }
    __syncthreads();
    int tc = t & 15, td = t >> 4;
    float acc[3][3];
#pragma unroll
    for (int i = 0; i < 3; i++)
#pragma unroll
        for (int j = 0; j < 3; j++) acc[i][j] = 0.0f;
    for (int p = 0; p < 256; p++) {
        float qv[3], kv[3];
#pragma unroll
        for (int i = 0; i < 3; i++) qv[i] = qs[(tc + 16 * i) * 257 + p];
#pragma unroll
        for (int j = 0; j < 3; j++) kv[j] = ks[(td + 16 * j) * 257 + p];
#pragma unroll
        for (int i = 0; i < 3; i++)
#pragma unroll
            for (int j = 0; j < 3; j++) acc[i][j] = fmaf(qv[i], kv[j], acc[i][j]);
    }
    float* outp = g_Spart + ((size_t)bh * 64 + ck) * 2304;
#pragma unroll
    for (int i = 0; i < 3; i++)
#pragma unroll
        for (int j = 0; j < 3; j++)
            outp[(tc + 16 * i) * 48 + td + 16 * j] = acc[i][j];
}

// K6: reduce partials, scale by 1/(|q||k|)*temp, softmax rows. grid(32), 256thr
__global__ void k6_softmax(const float* __restrict__ temp) {
    __shared__ float S[2304];
    __shared__ float iq[48], ik[48];
    int bh = blockIdx.x, b = bh >> 3, h = bh & 7, t = threadIdx.x;
    if (t < 48) iq[t] = 1.0f / fmaxf(sqrtf(g_red[(b * 3 + 0) * D1 + h * 48 + t]), 1e-12f);
    else if (t < 96) { int c = t - 48; ik[c] = 1.0f / fmaxf(sqrtf(g_red[(b * 3 + 1) * D1 + h * 48 + c]), 1e-12f); }
    __syncthreads();
    float tm = temp[h];
    for (int idx = t; idx < 2304; idx += 256) {
        float s = 0.0f;
        for (int k = 0; k < 64; k++) s += g_Spart[((size_t)bh * 64 + k) * 2304 + idx];
        S[idx] = s * iq[idx / 48] * ik[idx % 48] * tm;
    }
    __syncthreads();
    if (t < 48) {
        float m = -1e30f;
        for (int d = 0; d < 48; d++) m = fmaxf(m, S[t * 48 + d]);
        float sum = 0.0f;
        for (int d = 0; d < 48; d++) { float e = expf(S[t * 48 + d] - m); sum += e; S[t * 48 + d] = e; }
        float inv = 1.0f / sum;
        for (int d = 0; d < 48; d++) g_A[(size_t)bh * 2304 + t * 48 + d] = S[t * 48 + d] * inv;
    }
}

// K7: ao = attn @ v + L. grid(128,8,4), 192thr
__global__ __launch_bounds__(192) void k7_av() {
    __shared__ float A[2304];
    __shared__ float vs[48 * 128];
    int pt = blockIdx.x, h = blockIdx.y, b = blockIdx.z, t = threadIdx.x;
    int bh = b * 8 + h;
    for (int idx = t; idx < 2304; idx += 192) A[idx] = g_A[(size_t)bh * 2304 + idx];
    const float* vb = g_qkv + ((size_t)b * OC4 + 768 + h * 48) * HW + pt * 128;
    for (int idx = t; idx < 6144; idx += 192) {
        int d = idx >> 7, p = idx & 127;
        vs[d * 128 + p] = vb[(size_t)d * HW + p];
    }
    __syncthreads();
    int tp = t & 15, tc = t >> 4;  // tc 0..11
    float acc[4][8];
#pragma unroll
    for (int i = 0; i < 4; i++)
#pragma unroll
        for (int j = 0; j < 8; j++) acc[i][j] = 0.0f;
    for (int d = 0; d < 48; d++) {
        float av[4], vv[8];
#pragma unroll
        for (int i = 0; i < 4; i++) av[i] = A[(tc * 4 + i) * 48 + d];
#pragma unroll
        for (int j = 0; j < 8; j++) vv[j] = vs[d * 128 + tp + 16 * j];
#pragma unroll
        for (int i = 0; i < 4; i++)
#pragma unroll
            for (int j = 0; j < 8; j++) acc[i][j] = fmaf(av[i], vv[j], acc[i][j]);
    }
    float* ob = g_ao + ((size_t)b * D1 + h * 48) * HW + pt * 128;
#pragma unroll
    for (int i = 0; i < 4; i++) {
        float Lv = g_L[b * D1 + h * 48 + tc * 4 + i];
#pragma unroll
        for (int j = 0; j < 8; j++)
            ob[(size_t)(tc * 4 + i) * HW + tp + 16 * j] = acc[i][j] + Lv;
    }
}

// K8: final = po1 @ ao + x. grid(128,4), 256thr
__global__ __launch_bounds__(256) void k8_final(const float* __restrict__ x,
                                                const float* __restrict__ po1w,
                                                float* __restrict__ out) {
    __shared__ float Ws[64 * 48];
    __shared__ float As[64 * 128];
    int pt = blockIdx.x, b = blockIdx.y, t = threadIdx.x;
    int tp = t & 15, to = t >> 4;   // to 0..15, 3 out-channels each
    float acc[3][8];
#pragma unroll
    for (int i = 0; i < 3; i++)
#pragma unroll
        for (int j = 0; j < 8; j++) acc[i][j] = 0.0f;
    for (int cc = 0; cc < 6; cc++) {
        for (int idx = t; idx < 64 * 48; idx += 256) {
            int cl = idx / 48, o = idx % 48;
            Ws[cl * 48 + o] = po1w[o * 384 + cc * 64 + cl];
        }
        const float* ab = g_ao + ((size_t)b * D1 + cc * 64) * HW + pt * 128;
        for (int idx = t; idx < 64 * 128; idx += 256) {
            int c = idx >> 7, p = idx & 127;
            As[c * 128 + p] = ab[(size_t)c * HW + p];
        }
        __syncthreads();
        for (int c = 0; c < 64; c++) {
            float w[3], v[8];
#pragma unroll
            for (int i = 0; i < 3; i++) w[i] = Ws[c * 48 + to * 3 + i];
#pragma unroll
            for (int j = 0; j < 8; j++) v[j] = As[c * 128 + tp + 16 * j];
#pragma unroll
            for (int i = 0; i < 3; i++)
#pragma unroll
                for (int j = 0; j < 8; j++) acc[i][j] = fmaf(w[i], v[j], acc[i][j]);
        }
        __syncthreads();
    }
    const float* xb = x + (size_t)b * CD * HW + pt * 128;
    float* ob = out + (size_t)b * CD * HW + pt * 128;
#pragma unroll
    for (int i = 0; i < 3; i++) {
        int o = to * 3 + i;
#pragma unroll
        for (int j = 0; j < 8; j++) {
            int p = tp + 16 * j;
            ob[(size_t)o * HW + p] = acc[i][j] + xb[(size_t)o * HW + p];
        }
    }
}

extern "C" void kernel_launch(void* const* d_in, const int* in_sizes, int n_in,
                              void* d_out, int out_size) {
    const float* x    = (const float*)d_in[0];
    const float* qkvw = (const float*)d_in[1];
    const float* dww  = (const float*)d_in[2];
    const float* po1w = (const float*)d_in[3];
    const float* fc1w = (const float*)d_in[4];
    const float* fc1b = (const float*)d_in[5];
    const float* fc2w = (const float*)d_in[6];
    const float* fc2b = (const float*)d_in[7];
    const float* temp = (const float*)d_in[8];
    float* out = (float*)d_out;

    cudaFuncSetAttribute(k1_conv1x1, cudaFuncAttributeMaxDynamicSharedMemorySize, 49152);
    cudaFuncSetAttribute(k2_dwconv,  cudaFuncAttributeMaxDynamicSharedMemorySize, 141696);
    cudaFuncSetAttribute(k5_scores,  cudaFuncAttributeMaxDynamicSharedMemorySize, 98688);

    k1_conv1x1<<<dim3(128, 12, 4), 256, 49152>>>(x, qkvw);
    k2_dwconv <<<dim3(4, 192, 4), 256, 141696>>>(dww);
    k3_reduce <<<dim3(384, 3, 4), 256>>>();
    k4_mlp    <<<4, 384>>>(fc1w, fc1b, fc2w, fc2b);
    k5_scores <<<dim3(64, 32), 256, 98688>>>();
    k6_softmax<<<32, 256>>>(temp);
    k7_av     <<<dim3(128, 8, 4), 192>>>();
    k8_final  <<<dim3(128, 4), 256>>>(x, po1w, out);
}

// round 13
// speedup vs baseline: 1.5106x; 1.5106x over previous
#include <cuda_runtime.h>
#include <cuda_fp16.h>
#include <cuda_bf16.h>

#define BB  4
#define CD  48
#define HW  16384
#define D1  384
#define OC4 1536

__device__ __half g_qkv0[(size_t)BB * OC4 * HW];   // after 1x1 conv (fp16)
__device__ __half g_qkv [(size_t)BB * OC4 * HW];   // after dw conv (fp16)
__device__ float g_ao  [(size_t)BB * D1  * HW];
__device__ float g_red [BB * 3 * D1];
__device__ float g_L   [BB * D1];
__device__ float g_Spart[(size_t)BB * 8 * 64 * 2304];
__device__ float g_A   [(size_t)BB * 8 * 2304];

// K1: 1x1 conv 48->1536, HFMA2 over pixel pairs. grid(128,12,4), 256thr, dyn smem 36864
__global__ __launch_bounds__(256) void k1_conv1x1(const float* __restrict__ x,
                                                  const float* __restrict__ qw) {
    extern __shared__ char smc[];
    __half2* Wh = (__half2*)smc;                 // [48][128] dup weight pairs
    __half2* Xs = (__half2*)(smc + 48 * 128 * 4); // [48][64] pixel pairs
    int b = blockIdx.z, ot = blockIdx.y, pt = blockIdx.x, t = threadIdx.x;
    for (int idx = t; idx < 48 * 128; idx += 256) {
        int o = idx / 48, k = idx % 48;
        Wh[k * 128 + o] = __float2half2_rn(qw[(ot * 128 + o) * 48 + k]);
    }
    const float* xb = x + (size_t)b * CD * HW + pt * 128;
    for (int idx = t; idx < 48 * 64; idx += 256) {
        int k = idx / 64, pp = idx % 64;
        float2 v = ((const float2*)(xb + (size_t)k * HW))[pp];
        Xs[k * 64 + pp] = __floats2half2_rn(v.x, v.y);
    }
    __syncthreads();
    int tp = t & 15, ot8 = t >> 4;
    __half2 acc[8][4];
#pragma unroll
    for (int i = 0; i < 8; i++)
#pragma unroll
        for (int j = 0; j < 4; j++) acc[i][j] = __floats2half2_rn(0.f, 0.f);
    for (int k = 0; k < 48; k++) {
        __half2 xp[4];
#pragma unroll
        for (int j = 0; j < 4; j++) xp[j] = Xs[k * 64 + tp + 16 * j];
#pragma unroll
        for (int i = 0; i < 8; i++) {
            __half2 w2 = Wh[k * 128 + ot8 * 8 + i];
#pragma unroll
            for (int j = 0; j < 4; j++) acc[i][j] = __hfma2(xp[j], w2, acc[i][j]);
        }
    }
    __half* outb = g_qkv0 + ((size_t)b * OC4 + ot * 128) * HW + pt * 128;
#pragma unroll
    for (int i = 0; i < 8; i++) {
        __half2* orow = (__half2*)(outb + (size_t)(ot8 * 8 + i) * HW);
#pragma unroll
        for (int j = 0; j < 4; j++) orow[tp + 16 * j] = acc[i][j];
    }
}

// K2: grouped 3x3 conv, HFMA2 over oc pairs. grid(4,192,4), 256thr, dyn smem 70848
__global__ __launch_bounds__(256) void k2_dwconv(const float* __restrict__ dw) {
    extern __shared__ char smc[];
    __half*  sx = (__half*)smc;                      // [8][66][66] halo
    __half2* wp = (__half2*)(smc + 8 * 66 * 66 * 2); // [8 il][9 tap][4 oc-pair]
    int tileid = blockIdx.x, g = blockIdx.y, b = blockIdx.z, t = threadIdx.x;
    int ty0 = (tileid >> 1) * 64, tx0 = (tileid & 1) * 64;
    const __half* inb = g_qkv0 + ((size_t)b * OC4 + g * 8) * HW;
    for (int idx = t; idx < 8 * 66 * 66; idx += 256) {
        int ch = idx / (66 * 66), rem = idx % (66 * 66);
        int yy = rem / 66, xx = rem % 66;
        int gy = ty0 + yy - 1, gx = tx0 + xx - 1;
        __half v = __float2half(0.0f);
        if (gy >= 0 && gy < 128 && gx >= 0 && gx < 128) v = inb[(size_t)ch * HW + gy * 128 + gx];
        sx[idx] = v;
    }
    // FIX: strided loop (288 entries > 256 threads; the old `if (t<288)` left
    // wp[256..287] uninitialized -> garbage weights for input lane 7).
    for (int idx = t; idx < 288; idx += 256) {
        int il = idx / 36, rem = idx % 36, tap = rem / 4, op = rem % 4;
        wp[idx] = __floats2half2_rn(dw[(g * 8 + 2 * op) * 72 + il * 9 + tap],
                                    dw[(g * 8 + 2 * op + 1) * 72 + il * 9 + tap]);
    }
    __syncthreads();
    __half* outb = g_qkv + ((size_t)b * OC4 + g * 8) * HW;
    for (int s0 = 0; s0 < 2; s0++) {
        int s = t + s0 * 256, sy = s >> 3, x0 = (s & 7) * 8;
        __half2 acc[8][4];   // [px][oc-pair]
#pragma unroll
        for (int px = 0; px < 8; px++)
#pragma unroll
            for (int op = 0; op < 4; op++) acc[px][op] = __floats2half2_rn(0.f, 0.f);
        for (int il = 0; il < 8; il++) {
            const __half* base = sx + il * 66 * 66;
#pragma unroll
            for (int ky = 0; ky < 3; ky++) {
                const __half* row = base + (sy + ky) * 66 + x0;
                __half2 d[10];
#pragma unroll
                for (int m = 0; m < 10; m++) d[m] = __half2half2(row[m]);
#pragma unroll
                for (int kx = 0; kx < 3; kx++) {
                    int tap = ky * 3 + kx;
                    __half2 w0 = wp[il * 36 + tap * 4 + 0], w1 = wp[il * 36 + tap * 4 + 1];
                    __half2 w2 = wp[il * 36 + tap * 4 + 2], w3 = wp[il * 36 + tap * 4 + 3];
#pragma unroll
                    for (int px = 0; px < 8; px++) {
                        __half2 v = d[px + kx];
                        acc[px][0] = __hfma2(v, w0, acc[px][0]);
                        acc[px][1] = __hfma2(v, w1, acc[px][1]);
                        acc[px][2] = __hfma2(v, w2, acc[px][2]);
                        acc[px][3] = __hfma2(v, w3, acc[px][3]);
                    }
                }
            }
        }
        int off = (ty0 + sy) * 128 + tx0 + x0;
#pragma unroll
        for (int op = 0; op < 4; op++) {
            __half2* oL = (__half2*)(outb + (size_t)(2 * op) * HW + off);
            __half2* oH = (__half2*)(outb + (size_t)(2 * op + 1) * HW + off);
#pragma unroll
            for (int pp = 0; pp < 4; pp++) {
                oL[pp] = __halves2half2(__low2half(acc[2 * pp][op]),  __low2half(acc[2 * pp + 1][op]));
                oH[pp] = __halves2half2(__high2half(acc[2 * pp][op]), __high2half(acc[2 * pp + 1][op]));
            }
        }
    }
}

// K3: q sumsq / k sumsq / l sum (fp32 accum from fp16). grid(384,3,4), 256thr
__global__ void k3_reduce() {
    int ch = blockIdx.x, type = blockIdx.y, b = blockIdx.z, t = threadIdx.x;
    int base_ch = (type == 0) ? ch : (type == 1) ? 384 + ch : 1152 + ch;
    const __half* src = g_qkv + ((size_t)b * OC4 + base_ch) * HW;
    float s = 0.0f;
    for (int p = t; p < HW; p += 256) {
        float v = __half2float(src[p]);
        s += (type == 2) ? v : v * v;
    }
    __shared__ float red[256];
    red[t] = s; __syncthreads();
    for (int off = 128; off > 0; off >>= 1) { if (t < off) red[t] += red[t + off]; __syncthreads(); }
    if (t == 0) g_red[(b * 3 + type) * D1 + ch] = red[0];
}

// K4: channel MLP -> L (swish). grid(4), 384thr
__global__ void k4_mlp(const float* __restrict__ fc1w, const float* __restrict__ fc1b,
                       const float* __restrict__ fc2w, const float* __restrict__ fc2b) {
    int b = blockIdx.x, t = threadIdx.x;
    __shared__ float avg[384], y1[24];
    avg[t] = g_red[(b * 3 + 2) * D1 + t] * (1.0f / 16384.0f);
    __syncthreads();
    if (t < 24) {
        float s = fc1b[t];
        for (int c = 0; c < 384; c++) s += fc1w[t * 384 + c] * avg[c];
        y1[t] = fmaxf(s, 0.0f);
    }
    __syncthreads();
    float s = fc2b[t];
    for (int j = 0; j < 24; j++) s += fc2w[t * 24 + j] * y1[j];
    g_L[b * D1 + t] = s / (1.0f + expf(-s));
}

// K5: raw q.k^T partials (fp32 accum). grid(64,32), 256thr, dyn smem 98688
__global__ __launch_bounds__(256) void k5_scores() {
    extern __shared__ float sm[];
    float* qs = sm;            // [48][257]
    float* ks = sm + 48 * 257;
    int ck = blockIdx.x, bh = blockIdx.y, b = bh >> 3, h = bh & 7;
    int p0 = ck * 256, t = threadIdx.x;
    const __half* qb = g_qkv + ((size_t)b * OC4 + h * 48) * HW + p0;
    const __half* kb = g_qkv + ((size_t)b * OC4 + 384 + h * 48) * HW + p0;
    for (int idx = t; idx < 48 * 256; idx += 256) {
        int c = idx >> 8, p = idx & 255;
        qs[c * 257 + p] = __half2float(qb[(size_t)c * HW + p]);
        ks[c * 257 + p] = __half2float(kb[(size_t)c * HW + p]);
    }
    __syncthreads();
    int tc = t & 15, td = t >> 4;
    float acc[3][3];
#pragma unroll
    for (int i = 0; i < 3; i++)
#pragma unroll
        for (int j = 0; j < 3; j++) acc[i][j] = 0.0f;
    for (int p = 0; p < 256; p++) {
        float qv[3], kv[3];
#pragma unroll
        for (int i = 0; i < 3; i++) qv[i] = qs[(tc + 16 * i) * 257 + p];
#pragma unroll
        for (int j = 0; j < 3; j++) kv[j] = ks[(td + 16 * j) * 257 + p];
#pragma unroll
        for (int i = 0; i < 3; i++)
#pragma unroll
            for (int j = 0; j < 3; j++) acc[i][j] = fmaf(qv[i], kv[j], acc[i][j]);
    }
    float* outp = g_Spart + ((size_t)bh * 64 + ck) * 2304;
#pragma unroll
    for (int i = 0; i < 3; i++)
#pragma unroll
        for (int j = 0; j < 3; j++)
            outp[(tc + 16 * i) * 48 + td + 16 * j] = acc[i][j];
}

// K6: reduce partials, scale, softmax rows. grid(32), 256thr
__global__ void k6_softmax(const float* __restrict__ temp) {
    __shared__ float S[2304];
    __shared__ float iq[48], ik[48];
    int bh = blockIdx.x, b = bh >> 3, h = bh & 7, t = threadIdx.x;
    if (t < 48) iq[t] = 1.0f / fmaxf(sqrtf(g_red[(b * 3 + 0) * D1 + h * 48 + t]), 1e-12f);
    else if (t < 96) { int c = t - 48; ik[c] = 1.0f / fmaxf(sqrtf(g_red[(b * 3 + 1) * D1 + h * 48 + c]), 1e-12f); }
    __syncthreads();
    float tm = temp[h];
    for (int idx = t; idx < 2304; idx += 256) {
        float s = 0.0f;
        for (int k = 0; k < 64; k++) s += g_Spart[((size_t)bh * 64 + k) * 2304 + idx];
        S[idx] = s * iq[idx / 48] * ik[idx % 48] * tm;
    }
    __syncthreads();
    if (t < 48) {
        float m = -1e30f;
        for (int d = 0; d < 48; d++) m = fmaxf(m, S[t * 48 + d]);
        float sum = 0.0f;
        for (int d = 0; d < 48; d++) { float e = expf(S[t * 48 + d] - m); sum += e; S[t * 48 + d] = e; }
        float inv = 1.0f / sum;
        for (int d = 0; d < 48; d++) g_A[(size_t)bh * 2304 + t * 48 + d] = S[t * 48 + d] * inv;
    }
}

// K7: ao = attn @ v + L. grid(128,8,4), 192thr
__global__ __launch_bounds__(192) void k7_av() {
    __shared__ float A[2304];
    __shared__ float vs[48 * 128];
    int pt = blockIdx.x, h = blockIdx.y, b = blockIdx.z, t = threadIdx.x;
    int bh = b * 8 + h;
    for (int idx = t; idx < 2304; idx += 192) A[idx] = g_A[(size_t)bh * 2304 + idx];
    const __half* vb = g_qkv + ((size_t)b * OC4 + 768 + h * 48) * HW + pt * 128;
    for (int idx = t; idx < 6144; idx += 192) {
        int d = idx >> 7, p = idx & 127;
        vs[d * 128 + p] = __half2float(vb[(size_t)d * HW + p]);
    }
    __syncthreads();
    int tp = t & 15, tc = t >> 4;  // tc 0..11
    float acc[4][8];
#pragma unroll
    for (int i = 0; i < 4; i++)
#pragma unroll
        for (int j = 0; j < 8; j++) acc[i][j] = 0.0f;
    for (int d = 0; d < 48; d++) {
        float av[4], vv[8];
#pragma unroll
        for (int i = 0; i < 4; i++) av[i] = A[(tc * 4 + i) * 48 + d];
#pragma unroll
        for (int j = 0; j < 8; j++) vv[j] = vs[d * 128 + tp + 16 * j];
#pragma unroll
        for (int i = 0; i < 4; i++)
#pragma unroll
            for (int j = 0; j < 8; j++) acc[i][j] = fmaf(av[i], vv[j], acc[i][j]);
    }
    float* ob = g_ao + ((size_t)b * D1 + h * 48) * HW + pt * 128;
#pragma unroll
    for (int i = 0; i < 4; i++) {
        float Lv = g_L[b * D1 + h * 48 + tc * 4 + i];
#pragma unroll
        for (int j = 0; j < 8; j++)
            ob[(size_t)(tc * 4 + i) * HW + tp + 16 * j] = acc[i][j] + Lv;
    }
}

// K8: final = po1 @ ao + x. grid(128,4), 256thr
__global__ __launch_bounds__(256) void k8_final(const float* __restrict__ x,
                                                const float* __restrict__ po1w,
                                                float* __restrict__ out) {
    __shared__ float Ws[64 * 48];
    __shared__ float As[64 * 128];
    int pt = blockIdx.x, b = blockIdx.y, t = threadIdx.x;
    int tp = t & 15, to = t >> 4;   // to 0..15, 3 out-channels each
    float acc[3][8];
#pragma unroll
    for (int i = 0; i < 3; i++)
#pragma unroll
        for (int j = 0; j < 8; j++) acc[i][j] = 0.0f;
    for (int cc = 0; cc < 6; cc++) {
        for (int idx = t; idx < 64 * 48; idx += 256) {
            int cl = idx / 48, o = idx % 48;
            Ws[cl * 48 + o] = po1w[o * 384 + cc * 64 + cl];
        }
        const float* ab = g_ao + ((size_t)b * D1 + cc * 64) * HW + pt * 128;
        for (int idx = t; idx < 64 * 128; idx += 256) {
            int c = idx >> 7, p = idx & 127;
            As[c * 128 + p] = ab[(size_t)c * HW + p];
        }
        __syncthreads();
        for (int c = 0; c < 64; c++) {
            float w[3], v[8];
#pragma unroll
            for (int i = 0; i < 3; i++) w[i] = Ws[c * 48 + to * 3 + i];
#pragma unroll
            for (int j = 0; j < 8; j++) v[j] = As[c * 128 + tp + 16 * j];
#pragma unroll
            for (int i = 0; i < 3; i++)
#pragma unroll
                for (int j = 0; j < 8; j++) acc[i][j] = fmaf(w[i], v[j], acc[i][j]);
        }
        __syncthreads();
    }
    const float* xb = x + (size_t)b * CD * HW + pt * 128;
    float* ob = out + (size_t)b * CD * HW + pt * 128;
#pragma unroll
    for (int i = 0; i < 3; i++) {
        int o = to * 3 + i;
#pragma unroll
        for (int j = 0; j < 8; j++) {
            int p = tp + 16 * j;
            ob[(size_t)o * HW + p] = acc[i][j] + xb[(size_t)o * HW + p];
        }
    }
}

extern "C" void kernel_launch(void* const* d_in, const int* in_sizes, int n_in,
                              void* d_out, int out_size) {
    const float* x    = (const float*)d_in[0];
    const float* qkvw = (const float*)d_in[1];
    const float* dww  = (const float*)d_in[2];
    const float* po1w = (const float*)d_in[3];
    const float* fc1w = (const float*)d_in[4];
    const float* fc1b = (const float*)d_in[5];
    const float* fc2w = (const float*)d_in[6];
    const float* fc2b = (const float*)d_in[7];
    const float* temp = (const float*)d_in[8];
    float* out = (float*)d_out;

    cudaFuncSetAttribute(k1_conv1x1, cudaFuncAttributeMaxDynamicSharedMemorySize, 36864);
    cudaFuncSetAttribute(k2_dwconv,  cudaFuncAttributeMaxDynamicSharedMemorySize, 70848);
    cudaFuncSetAttribute(k5_scores,  cudaFuncAttributeMaxDynamicSharedMemorySize, 98688);

    k1_conv1x1<<<dim3(128, 12, 4), 256, 36864>>>(x, qkvw);
    k2_dwconv <<<dim3(4, 192, 4), 256, 70848>>>(dww);
    k3_reduce <<<dim3(384, 3, 4), 256>>>();
    k4_mlp    <<<4, 384>>>(fc1w, fc1b, fc2w, fc2b);
    k5_scores <<<dim3(64, 32), 256, 98688>>>();
    k6_softmax<<<32, 256>>>(temp);
    k7_av     <<<dim3(128, 8, 4), 192>>>();
    k8_final  <<<dim3(128, 4), 256>>>(x, po1w, out);
}